// round 6
// baseline (speedup 1.0000x reference)
#include <cuda_runtime.h>
#include <cuda_fp16.h>
#include <cstdint>

#define T_  256
#define NN  4000
#define DM  178
#define DI  46
#define H_  64
#define DH  64
#define FF  110   // DI + H
#define G4  256   // 4*H
#define NCHUNK (T_ * 125)   // 32000 chunks of 32 rows (4000 = 125*32)
#define GRID_MLP 296

typedef unsigned long long u64;

// ---------- device scratch ----------
__device__ float g_XZ[T_ * G4];
__device__ float g_W1m[64 * 64];     // W1[:,DI:] contiguous, 16B-aligned rows
__device__ float g_macro1[T_ * DH];
__device__ float g_sum[T_];
__device__ float g_cnt[T_];
__device__ int   g_mask_kind;        // 0=uint8/bool, 1=int32, 2=float32
__device__ int   g_tick = 0;         // warp work-stealing ticket (reset by k_final)
__device__ int   g_prog = -1;        // highest t with macro1 published (reset by k_final)

// ---------- packed f32x2 helpers ----------
__device__ __forceinline__ u64 pk2(float lo, float hi) {
    u64 r; asm("mov.b64 %0, {%1, %2};" : "=l"(r) : "f"(lo), "f"(hi)); return r;
}
__device__ __forceinline__ u64 ffma2(u64 a, u64 b, u64 c) {
    u64 d; asm("fma.rn.f32x2 %0, %1, %2, %3;" : "=l"(d) : "l"(a), "l"(b), "l"(c)); return d;
}
__device__ __forceinline__ float2 up2(u64 a) {
    float2 f; asm("mov.b64 {%0, %1}, %2;" : "=f"(f.x), "=f"(f.y) : "l"(a)); return f;
}

// ---------- activations ----------
__device__ __forceinline__ float sigm(float x) {
    float e = exp2f(-1.44269504088896340736f * x);
    return __fdividef(1.0f, 1.0f + e);
}
__device__ __forceinline__ float tanh_(float x) {
    float a = fabsf(x);
    float e = exp2f(-2.88539008177792681472f * a);
    float r = __fdividef(1.0f - e, 1.0f + e);
    return copysignf(r, x);
}

// ---------- warp MMA helpers ----------
__device__ __forceinline__ uint32_t smem_u32(const void* p) {
    uint32_t a;
    asm("{ .reg .u64 t; cvta.to.shared.u64 t, %1; cvt.u32.u64 %0, t; }" : "=r"(a) : "l"(p));
    return a;
}
__device__ __forceinline__ void ldsm4(uint32_t* r, uint32_t addr) {
    asm volatile("ldmatrix.sync.aligned.m8n8.x4.shared.b16 {%0,%1,%2,%3}, [%4];"
        : "=r"(r[0]), "=r"(r[1]), "=r"(r[2]), "=r"(r[3]) : "r"(addr));
}
__device__ __forceinline__ void mma16816(float* d, const uint32_t* a, const uint32_t* b) {
    asm volatile("mma.sync.aligned.m16n8k16.row.col.f32.f16.f16.f32 "
        "{%0,%1,%2,%3}, {%4,%5,%6,%7}, {%8,%9}, {%0,%1,%2,%3};"
        : "+f"(d[0]), "+f"(d[1]), "+f"(d[2]), "+f"(d[3])
        : "r"(a[0]), "r"(a[1]), "r"(a[2]), "r"(a[3]), "r"(b[0]), "r"(b[1]));
}
__device__ __forceinline__ uint32_t pkhf(__half a, __half b) {
    return ((uint32_t)__half_as_ushort(b) << 16) | (uint32_t)__half_as_ushort(a);
}
__device__ __forceinline__ void split_hf(float x, __half& h, __half& l) {
    h = __float2half_rn(x);
    l = __float2half_rn(x - __half2float(h));
}
// XOR SW128 swizzle: 128B rows of 64 fp16 (8 chunks of 16B)
__device__ __forceinline__ uint32_t xaddr(int r, int c) {
    return (uint32_t)(r * 128 + ((c ^ (r & 7)) << 4));
}
__device__ __forceinline__ void cp16(uint32_t saddr, const void* gaddr) {
    asm volatile("cp.async.cg.shared.global [%0], [%1], 16;" :: "r"(saddr), "l"(gaddr));
}
__device__ __forceinline__ int ld_acq(const int* p) {
    int v; asm volatile("ld.acquire.gpu.global.b32 %0, [%1];" : "=r"(v) : "l"(p)); return v;
}
__device__ __forceinline__ void st_rel(int* p, int v) {
    asm volatile("st.release.gpu.global.b32 [%0], %1;" :: "l"(p), "r"(v) : "memory");
}

// ---------- K1: XZ precompute + W1m copy + mask detect + accumulator zero ----------
__global__ void __launch_bounds__(256) k_prep(const float* __restrict__ macro,
                                              const float* __restrict__ W_ih,
                                              const float* __restrict__ b_ih,
                                              const float* __restrict__ b_hh,
                                              const float* __restrict__ W1,
                                              const unsigned char* __restrict__ masks) {
    __shared__ float xs[DM];
    int t = blockIdx.x, g = threadIdx.x;
    if (g < DM) xs[g] = macro[t * DM + g];
    if (g == 0) { g_sum[t] = 0.f; g_cnt[t] = 0.f; }
    __syncthreads();
    float acc = b_ih[g] + b_hh[g];
    const float2* wr = (const float2*)(W_ih + g * DM);
#pragma unroll 4
    for (int j = 0; j < DM / 2; j++) {
        float2 w = wr[j];
        acc = fmaf(xs[2 * j], w.x, acc);
        acc = fmaf(xs[2 * j + 1], w.y, acc);
    }
    g_XZ[t * G4 + g] = acc;

    if (blockIdx.x == 1) {   // compact copy of W1 macro columns
        for (int idx = g; idx < 64 * 64; idx += 256) {
            int o = idx >> 6, k = idx & 63;
            g_W1m[idx] = W1[o * FF + DI + k];
        }
    }
    if (blockIdx.x == 0) {
        __shared__ int s_any, s_flt;
        if (g == 0) { s_any = 0; s_flt = 0; }
        __syncthreads();
        int ta = 0, tf = 0;
        for (int j = g; j < 1024; j += 256) {
            unsigned char c1 = masks[4 * j + 1], c2 = masks[4 * j + 2], c3 = masks[4 * j + 3];
            if (c1 | c2 | c3) ta = 1;
            if (c3 == 0x3F) tf = 1;
        }
        if (ta) atomicOr(&s_any, 1);
        if (tf) atomicOr(&s_flt, 1);
        __syncthreads();
        if (g == 0) g_mask_kind = s_flt ? 2 : (s_any ? 0 : 1);
    }
}

// ---------- fused MLP + producer LSTM ----------
// smem map (bytes):
#define SM_XHI 0            // 128 rows x 128B (per-warp 32-row regions)
#define SM_XLO 16384
#define SM_W1H 32768        // 64 x 128B each
#define SM_W1L 40960
#define SM_W2H 49152
#define SM_W2L 57344
#define SM_RAW 65536        // 8 slabs (4 warps x 2 bufs) x 5888B
#define SM_WROW 112640      // 128 floats
#define SMEM_MLP 113152

// one layer: 3-term fp16 split (ah*bh + al*bh + ah*bl); warp-local m=32
template<int KC>
__device__ __forceinline__ void do_layer(
    uint32_t sb, uint32_t aH, uint32_t aL, uint32_t bH, uint32_t bL,
    const float* iv, float acc[2][8][4],
    int wid, int a_ro, int a_co, int b_ro, int b_co)
{
#pragma unroll
    for (int mi = 0; mi < 2; mi++)
#pragma unroll
        for (int ni = 0; ni < 8; ni++) {
            acc[mi][ni][0] = iv[2 * ni];
            acc[mi][ni][1] = iv[2 * ni + 1];
            acc[mi][ni][2] = iv[2 * ni];
            acc[mi][ni][3] = iv[2 * ni + 1];
        }
#pragma unroll
    for (int kc = 0; kc < KC; kc++) {
        uint32_t ah[2][4], al[2][4], bh[4][4], bl[4][4];
#pragma unroll
        for (int mi = 0; mi < 2; mi++) {
            uint32_t off = xaddr(wid * 32 + mi * 16 + a_ro, 2 * kc + a_co);
            ldsm4(ah[mi], sb + aH + off);
            ldsm4(al[mi], sb + aL + off);
        }
#pragma unroll
        for (int np = 0; np < 4; np++) {
            uint32_t off = xaddr(np * 16 + b_ro, 2 * kc + b_co);
            ldsm4(bh[np], sb + bH + off);
            ldsm4(bl[np], sb + bL + off);
        }
#pragma unroll
        for (int mi = 0; mi < 2; mi++)
#pragma unroll
            for (int ni = 0; ni < 8; ni++)
                mma16816(acc[mi][ni], ah[mi], &bh[ni >> 1][(ni & 1) * 2]);
#pragma unroll
        for (int mi = 0; mi < 2; mi++)
#pragma unroll
            for (int ni = 0; ni < 8; ni++)
                mma16816(acc[mi][ni], al[mi], &bh[ni >> 1][(ni & 1) * 2]);
#pragma unroll
        for (int mi = 0; mi < 2; mi++)
#pragma unroll
            for (int ni = 0; ni < 8; ni++)
                mma16816(acc[mi][ni], ah[mi], &bl[ni >> 1][(ni & 1) * 2]);
    }
}

__global__ void __launch_bounds__(128, 2)
k_mlp(const float* __restrict__ indiv, const unsigned char* __restrict__ mask_raw,
      const float* __restrict__ rets,
      const float* __restrict__ W_hh, const float* __restrict__ b1,
      const float* __restrict__ W1, const float* __restrict__ W2,
      const float* __restrict__ b2, const float* __restrict__ W3,
      const float* __restrict__ b3, float* __restrict__ out_w)
{
    extern __shared__ char sm[];
    const uint32_t sb = smem_u32(sm);

    const int tid = threadIdx.x;
    const int wid = tid >> 5, lane = tid & 31;
    const int lq = lane & 7, qq = lane >> 3;
    const int a_ro = lq + ((qq & 1) << 3), a_co = qq >> 1;
    const int b_ro = lq + ((qq >> 1) << 3), b_co = qq & 1;
    const int cpair = (lane & 3) * 2;

    // ---- one-time weight staging (fp16 hi/lo, zero-pad K) ----
    for (int idx = tid; idx < 64 * 64; idx += 128) {
        int n = idx >> 6, k = idx & 63;
        float v1 = (k < DI) ? W1[n * FF + k] : 0.f;
        float v2 = W2[idx];
        uint32_t o = xaddr(n, k >> 3) + (k & 7) * 2;
        __half h, l;
        split_hf(v1, h, l);
        *(__half*)(sm + SM_W1H + o) = h;
        *(__half*)(sm + SM_W1L + o) = l;
        split_hf(v2, h, l);
        *(__half*)(sm + SM_W2H + o) = h;
        *(__half*)(sm + SM_W2L + o) = l;
    }
    float b2v[16], w3v[16];
#pragma unroll
    for (int ni = 0; ni < 8; ni++) {
        b2v[2 * ni]     = b2[ni * 8 + cpair];
        b2v[2 * ni + 1] = b2[ni * 8 + cpair + 1];
        w3v[2 * ni]     = W3[ni * 8 + cpair];
        w3v[2 * ni + 1] = W3[ni * 8 + cpair + 1];
    }
    const float b3v = b3[0];
    const int mask_kind = g_mask_kind;
    __syncthreads();

    // ================= CTA 0: LSTM producer =================
    if (blockIdx.x == 0) {
        float* h_s = (float*)(sm + SM_RAW);        // 64 floats
        float* p_s = h_s + 64;                     // 64 floats (i*g products)
        const int r0 = tid, r1 = tid + 128;        // gate rows: (i|f) and (g|o)
        u64 w0[32], w1[32];
        {
            const float4* a = (const float4*)(W_hh + r0 * H_);
            const float4* b = (const float4*)(W_hh + r1 * H_);
#pragma unroll
            for (int j = 0; j < 16; j++) {
                float4 va = a[j], vb = b[j];
                w0[2 * j] = pk2(va.x, va.y); w0[2 * j + 1] = pk2(va.z, va.w);
                w1[2 * j] = pk2(vb.x, vb.y); w1[2 * j + 1] = pk2(vb.z, vb.w);
            }
        }
        const float b1v = (tid < 64) ? b1[tid] : 0.f;
        float c = 0.f;
        if (tid < 64) h_s[tid] = 0.f;
        float z0 = g_XZ[r0], z1 = g_XZ[r1];
        __syncthreads();

        for (int t = 0; t < T_; t++) {
            // gemv over h_{t-1}
            u64 a00 = pk2(0.f, 0.f), a01 = a00, a10 = a00, a11 = a00;
            const float4* h4 = (const float4*)h_s;
#pragma unroll
            for (int j = 0; j < 16; j++) {
                float4 hv = h4[j];
                u64 hp0 = pk2(hv.x, hv.y), hp1 = pk2(hv.z, hv.w);
                a00 = ffma2(w0[2 * j], hp0, a00);
                a01 = ffma2(w0[2 * j + 1], hp1, a01);
                a10 = ffma2(w1[2 * j], hp0, a10);
                a11 = ffma2(w1[2 * j + 1], hp1, a11);
            }
            u64 one = pk2(1.f, 1.f);
            a00 = ffma2(one, a01, a00);
            a10 = ffma2(one, a11, a10);
            float2 s0 = up2(a00), s1 = up2(a10);
            float z0f = z0 + s0.x + s0.y;
            float z1f = z1 + s1.x + s1.y;
            if (t + 1 < T_) { z0 = g_XZ[(t + 1) * G4 + r0]; z1 = g_XZ[(t + 1) * G4 + r1]; }

            float fo0 = 0.f, fo1 = 0.f;
            if (tid < 64) {
                float iv = sigm(z0f), gv = tanh_(z1f);
                p_s[tid] = iv * gv;
            } else {
                fo0 = sigm(z0f);   // f
                fo1 = sigm(z1f);   // o
            }
            __syncthreads();       // p ready
            if (tid >= 64) {
                int j = tid - 64;
                c = fmaf(fo0, c, p_s[j]);
                h_s[j] = fo1 * tanh_(c);
            }
            __syncthreads();       // h_t ready
            // macro1[t] = b1 + W1m @ h_t
            if (tid < 64) {
                const float4* wm = (const float4*)(g_W1m + tid * 64);
                u64 m0 = pk2(b1v, 0.f), m1 = pk2(0.f, 0.f);
#pragma unroll
                for (int j = 0; j < 16; j++) {
                    float4 w = __ldg(wm + j);
                    float4 hv = h4[j];
                    m0 = ffma2(pk2(w.x, w.y), pk2(hv.x, hv.y), m0);
                    m1 = ffma2(pk2(w.z, w.w), pk2(hv.z, hv.w), m1);
                }
                m0 = ffma2(one, m1, m0);
                float2 mm = up2(m0);
                g_macro1[t * DH + tid] = mm.x + mm.y;
                __threadfence();
            }
            __syncthreads();       // macro1 stores done (+fenced)
            if (tid == 0) st_rel(&g_prog, t);
        }
    }

    // ================= all warps: work-stealing MLP =================
    float* wrowW = (float*)(sm + SM_WROW) + wid * 32;
    const uint32_t slab0 = sb + SM_RAW + (uint32_t)(wid * 2) * 5888;
    float acc[2][8][4];

    auto grab = [&]() -> int {
        int c;
        if (lane == 0) c = atomicAdd(&g_tick, 1);
        return __shfl_sync(0xffffffffu, c, 0);
    };
    auto stage_issue = [&](int chunk, int buf) {
        int t = chunk / 125, p0 = (chunk % 125) * 32;
        const float4* gsrc = (const float4*)(indiv + ((size_t)t * NN + p0) * DI);
        uint32_t dst = slab0 + (uint32_t)buf * 5888;
#pragma unroll
        for (int i = lane; i < 368; i += 32)
            cp16(dst + (uint32_t)i * 16, gsrc + i);
        asm volatile("cp.async.commit_group;" ::: "memory");
    };

    int chunk = grab();
    int buf = 0;
    if (chunk < NCHUNK) stage_issue(chunk, buf);

    while (chunk < NCHUNK) {
        int nxt = grab();
        if (nxt < NCHUNK) {
            stage_issue(nxt, buf ^ 1);
            asm volatile("cp.async.wait_group 1;" ::: "memory");
        } else {
            asm volatile("cp.async.wait_group 0;" ::: "memory");
        }

        const int t = chunk / 125;
        const int p0 = (chunk % 125) * 32;
        const size_t gbase = (size_t)t * NN + p0;

        // wait until macro1[t] is published
        while (ld_acq(&g_prog) < t) __nanosleep(128);

        float m1v[16];
#pragma unroll
        for (int ni = 0; ni < 8; ni++) {
            m1v[2 * ni]     = g_macro1[t * DH + ni * 8 + cpair];
            m1v[2 * ni + 1] = g_macro1[t * DH + ni * 8 + cpair + 1];
        }

        // split own row (lane = row) into fp16 hi/lo, swizzled
        {
            const float* rp = (const float*)(sm + SM_RAW + (wid * 2 + buf) * 5888) + lane * DI;
            const int row = wid * 32 + lane;
#pragma unroll
            for (int cch = 0; cch < 6; cch++) {
                uint32_t hw[4], lw[4];
#pragma unroll
                for (int jp = 0; jp < 4; jp++) {
                    int c0 = cch * 8 + 2 * jp, c1 = c0 + 1;
                    float x0 = (c0 < DI) ? rp[c0] : 0.f;
                    float x1 = (c1 < DI) ? rp[c1] : 0.f;
                    __half h0, l0, h1, l1;
                    split_hf(x0, h0, l0);
                    split_hf(x1, h1, l1);
                    hw[jp] = pkhf(h0, h1);
                    lw[jp] = pkhf(l0, l1);
                }
                uint32_t off = xaddr(row, cch);
                *(uint4*)(sm + SM_XHI + off) = make_uint4(hw[0], hw[1], hw[2], hw[3]);
                *(uint4*)(sm + SM_XLO + off) = make_uint4(lw[0], lw[1], lw[2], lw[3]);
            }
        }
        __syncwarp();

        // layer 1: K=48
        do_layer<3>(sb, SM_XHI, SM_XLO, SM_W1H, SM_W1L, m1v, acc,
                    wid, a_ro, a_co, b_ro, b_co);
        __syncwarp();

        // epilogue 1: relu + split, write A1 back into own rows
#pragma unroll
        for (int mi = 0; mi < 2; mi++) {
            int R0 = wid * 32 + mi * 16 + (lane >> 2);
            int R1 = R0 + 8;
#pragma unroll
            for (int ni = 0; ni < 8; ni++) {
                float a0 = fmaxf(acc[mi][ni][0], 0.f);
                float a1 = fmaxf(acc[mi][ni][1], 0.f);
                float a2 = fmaxf(acc[mi][ni][2], 0.f);
                float a3 = fmaxf(acc[mi][ni][3], 0.f);
                __half h0, l0, h1, l1, h2, l2, h3, l3;
                split_hf(a0, h0, l0); split_hf(a1, h1, l1);
                split_hf(a2, h2, l2); split_hf(a3, h3, l3);
                uint32_t off0 = xaddr(R0, ni) + (lane & 3) * 4;
                uint32_t off1 = xaddr(R1, ni) + (lane & 3) * 4;
                *(uint32_t*)(sm + SM_XHI + off0) = pkhf(h0, h1);
                *(uint32_t*)(sm + SM_XLO + off0) = pkhf(l0, l1);
                *(uint32_t*)(sm + SM_XHI + off1) = pkhf(h2, h3);
                *(uint32_t*)(sm + SM_XLO + off1) = pkhf(l2, l3);
            }
        }
        __syncwarp();

        // layer 2: K=64
        do_layer<4>(sb, SM_XHI, SM_XLO, SM_W2H, SM_W2L, b2v, acc,
                    wid, a_ro, a_co, b_ro, b_co);

        // epilogue 2: w3 dot relu -> per-row weight
        float ws[4] = {0.f, 0.f, 0.f, 0.f};
#pragma unroll
        for (int mi = 0; mi < 2; mi++)
#pragma unroll
            for (int ni = 0; ni < 8; ni++) {
                ws[2 * mi]     = fmaf(w3v[2 * ni], fmaxf(acc[mi][ni][0], 0.f),
                                 fmaf(w3v[2 * ni + 1], fmaxf(acc[mi][ni][1], 0.f), ws[2 * mi]));
                ws[2 * mi + 1] = fmaf(w3v[2 * ni], fmaxf(acc[mi][ni][2], 0.f),
                                 fmaf(w3v[2 * ni + 1], fmaxf(acc[mi][ni][3], 0.f), ws[2 * mi + 1]));
            }
#pragma unroll
        for (int i = 0; i < 4; i++) {
            ws[i] += __shfl_xor_sync(0xffffffffu, ws[i], 1);
            ws[i] += __shfl_xor_sync(0xffffffffu, ws[i], 2);
        }
        if ((lane & 3) == 0) {
            int r = lane >> 2;
            wrowW[r] = ws[0]; wrowW[r + 8] = ws[1];
            wrowW[r + 16] = ws[2]; wrowW[r + 24] = ws[3];
        }
        __syncwarp();

        // per-point finish
        float contrib, mval;
        {
            float w = wrowW[lane] + b3v;
            size_t gi = gbase + lane;
            float mf = (mask_kind == 0) ? (float)mask_raw[gi]
                     : (mask_kind == 1) ? (float)((const int*)mask_raw)[gi]
                     : ((const float*)mask_raw)[gi];
            float wm = w * mf;
            out_w[gi] = wm;
            contrib = wm * rets[gi];
            mval = mf;
        }
#pragma unroll
        for (int off = 16; off; off >>= 1) {
            contrib += __shfl_down_sync(0xffffffffu, contrib, off);
            mval    += __shfl_down_sync(0xffffffffu, mval, off);
        }
        if (lane == 0) {
            atomicAdd(&g_sum[t], contrib);
            atomicAdd(&g_cnt[t], mval);
        }
        chunk = nxt;
        buf ^= 1;
    }
}

// ---------- K5: sdf finalize + flag reset for next launch ----------
__global__ void __launch_bounds__(256) k_final(float* __restrict__ out_sdf) {
    __shared__ float smr[256];
    int t = threadIdx.x;
    float cnt = g_cnt[t];
    smr[t] = cnt;
    __syncthreads();
    for (int s = 128; s > 0; s >>= 1) {
        if (t < s) smr[t] += smr[t + s];
        __syncthreads();
    }
    float mean = smr[0] * (1.0f / 256.0f);
    out_sdf[t] = g_sum[t] / cnt * mean + 1.0f;
    if (t == 0) { g_tick = 0; g_prog = -1; }   // reset producer/consumer state
}

// ---------- launch ----------
extern "C" void kernel_launch(void* const* d_in, const int* in_sizes, int n_in,
                              void* d_out, int out_size) {
    (void)in_sizes; (void)n_in; (void)out_size;
    const float* macro = (const float*)d_in[0];
    const float* indiv = (const float*)d_in[1];
    const unsigned char* masks = (const unsigned char*)d_in[2];
    const float* rets  = (const float*)d_in[3];
    const float* W_ih  = (const float*)d_in[4];
    const float* W_hh  = (const float*)d_in[5];
    const float* b_ih  = (const float*)d_in[6];
    const float* b_hh  = (const float*)d_in[7];
    const float* W1    = (const float*)d_in[8];
    const float* b1    = (const float*)d_in[9];
    const float* W2    = (const float*)d_in[10];
    const float* b2    = (const float*)d_in[11];
    const float* W3    = (const float*)d_in[12];
    const float* b3    = (const float*)d_in[13];

    float* out     = (float*)d_out;
    float* out_sdf = out;          // sdf [T,1]
    float* out_w   = out + T_;     // weights [1,T,N,1]

    cudaFuncSetAttribute(k_mlp, cudaFuncAttributeMaxDynamicSharedMemorySize, SMEM_MLP);

    k_prep<<<T_, G4>>>(macro, W_ih, b_ih, b_hh, W1, masks);
    k_mlp<<<GRID_MLP, 128, SMEM_MLP>>>(indiv, masks, rets, W_hh, b1,
                                       W1, W2, b2, W3, b3, out_w);
    k_final<<<1, T_>>>(out_sdf);
}